// round 15
// baseline (speedup 1.0000x reference)
#include <cuda_runtime.h>
#include <cuda_fp16.h>

#define BINS 10
#define GRID_BLOCKS 296          // 2 CTAs x 148 SMs, persistent single wave
#define BLOCK_THREADS 256

// Device-global scratch (no allocations allowed). Zero at module load;
// the in-kernel finalizer resets after every launch (graph-replay safe).
__device__ double       g_sum[BINS];   // cumulative: sum over bins >= k
__device__ unsigned int g_cnt[BINS];   // cumulative counts
__device__ unsigned int g_ticket;

// Thresholds in constant memory -> uniform-register path, zero thread-reg
// cost. Half bit patterns for:
// [-100 sentinel(validity), log2(1/9), -2, log2(3/7), log2(4/6), 0,
//  log2(6/4), log2(7/3), 2, log2(9)]   (bin>=k <=> q2 >= log2(k/(10-k)))
__constant__ unsigned int c_th2[BINS] = {
    0xD640D640u, 0xC257C257u, 0xC000C000u, 0xBCE4BCE4u, 0xB8AEB8AEu,
    0x00000000u, 0x38AE38AEu, 0x3CE43CE4u, 0x40004000u, 0x42574257u
};

// f32 front end per element. Log2 domain: q2 = p*(1-2t)*log2e.
//   |sigmoid(p)-t| = sigmoid(q),  bce = (q2 + log2(1+2^q2)) * ln2
// Invalid (w==0) elements get q2 = -1000 so every bin mask is false.
__device__ __forceinline__ void ghmc_elem(float p, float t, float w,
                                          float& q2m, float& bw) {
    const float L2E = 1.44269504089f;
    float sgnl = fmaf(-2.0f * L2E, t, L2E);   // (1-2t)*log2e
    float q2   = p * sgnl;
    q2m = (w > 0.0f) ? q2 : -1000.0f;
    float e2 = exp2f(q2);                     // MUFU.EX2, no pre-scale
    float l  = __log2f(1.0f + e2);            // FADD + MUFU.LG2
    bw = (q2 + l) * 0.69314718056f;           // softplus in natural units
}

// Pairwise half2 cumulative scatter: per threshold one compare-mask,
// one HFMA2 (sum += mask*bce), one HADD2 (count += mask).
__device__ __forceinline__ void ghmc_acc(__half2 qh, __half2 bh,
                                         __half2* hs, __half2* hc) {
#pragma unroll
    for (int k = 0; k < BINS; k++) {
        __half2 thk = *reinterpret_cast<const __half2*>(&c_th2[k]);
        __half2 m = __hge2(qh, thk);          // 1.0 / 0.0 per half
        hs[k] = __hfma2(m, bh, hs[k]);
        hc[k] = __hadd2(hc[k], m);
    }
}

__device__ __forceinline__ void ghmc_quad(const float4& p, const float4& t,
                                          const float4& w,
                                          __half2* hs, __half2* hc) {
    float qa, qb, ba, bb;
    ghmc_elem(p.x, t.x, w.x, qa, ba);
    ghmc_elem(p.y, t.y, w.y, qb, bb);
    ghmc_acc(__floats2half2_rn(qa, qb), __floats2half2_rn(ba, bb), hs, hc);
    ghmc_elem(p.z, t.z, w.z, qa, ba);
    ghmc_elem(p.w, t.w, w.w, qb, bb);
    ghmc_acc(__floats2half2_rn(qa, qb), __floats2half2_rn(ba, bb), hs, hc);
}

__global__ void __launch_bounds__(BLOCK_THREADS, 2)
ghmc_kernel(const float4* __restrict__ pred,
            const float4* __restrict__ targ,
            const float4* __restrict__ lw,
            float* __restrict__ out,
            int n4, int n_total) {
    __half2 hs[BINS], hc[BINS];
    const __half2 hzero = __halves2half2(__ushort_as_half(0), __ushort_as_half(0));
#pragma unroll
    for (int b = 0; b < BINS; b++) { hs[b] = hzero; hc[b] = hzero; }

    const int gid    = blockIdx.x * BLOCK_THREADS + threadIdx.x;
    const int stride = gridDim.x * BLOCK_THREADS;

    // Software-pipelined grid-stride loop, prefetch distance 1. With the
    // 128-reg budget of (256,2), ptxas can keep both batches live, so the
    // next iteration's 3 loads stay in flight throughout current compute.
    int  i  = gid;
    bool v0 = i < n4;
    float4 p0, t0, w0;
    if (v0) { p0 = pred[i]; t0 = targ[i]; w0 = lw[i]; }

    while (v0) {
        int  j  = i + stride;
        bool v1 = j < n4;
        float4 p1, t1, w1;
        if (v1) { p1 = pred[j]; t1 = targ[j]; w1 = lw[j]; }   // prefetch

        ghmc_quad(p0, t0, w0, hs, hc);                        // compute

        p0 = p1; t0 = t1; w0 = w1;
        i = j; v0 = v1;
    }

    // Scalar tail (n_total % 4): one thread, second slot invalidated.
    if (gid == 0) {
        const float* pf = (const float*)pred;
        const float* tf = (const float*)targ;
        const float* wf = (const float*)lw;
        for (int k = n4 * 4; k < n_total; k++) {
            float qa, ba;
            ghmc_elem(pf[k], tf[k], wf[k], qa, ba);
            ghmc_acc(__floats2half2_rn(qa, -1000.0f),
                     __floats2half2_rn(ba, 0.0f), hs, hc);
        }
    }

    // Unpack half2 accumulators to f32.
    // Per-thread per-bin counts <= ~360 (69 iters x 4 + tail): exact in half
    // (integers < 2048 exact).
    float s[BINS], c[BINS];
#pragma unroll
    for (int b = 0; b < BINS; b++) {
        float2 sf = __half22float2(hs[b]);
        float2 cf = __half22float2(hc[b]);
        s[b] = sf.x + sf.y;
        c[b] = cf.x + cf.y;
    }

    // Warp butterfly reduce (block counts <= 72k: exact in f32).
#pragma unroll
    for (int b = 0; b < BINS; b++)
#pragma unroll
        for (int off = 16; off > 0; off >>= 1) {
            s[b] += __shfl_xor_sync(0xffffffffu, s[b], off);
            c[b] += __shfl_xor_sync(0xffffffffu, c[b], off);
        }

    __shared__ float s_sum[BINS];
    __shared__ float s_cnt[BINS];
    if (threadIdx.x < BINS) { s_sum[threadIdx.x] = 0.0f; s_cnt[threadIdx.x] = 0.0f; }
    __syncthreads();

    if ((threadIdx.x & 31) == 0) {
#pragma unroll
        for (int b = 0; b < BINS; b++) {
            atomicAdd(&s_sum[b], s[b]);
            atomicAdd(&s_cnt[b], c[b]);
        }
    }
    __syncthreads();

    if (threadIdx.x < BINS) {
        atomicAdd(&g_sum[threadIdx.x], (double)s_sum[threadIdx.x]);
        atomicAdd(&g_cnt[threadIdx.x], (unsigned int)(s_cnt[threadIdx.x] + 0.5f));
    }
    __threadfence();
    __syncthreads();

    // Last block: cumulative -> per-bin, compute loss, reset globals.
    if (threadIdx.x == 0) {
        unsigned int done = atomicAdd(&g_ticket, 1u);
        if (done == gridDim.x - 1) {
            __threadfence();
            double loss = 0.0;
            int n = 0;
#pragma unroll
            for (int b = 0; b < BINS; b++) {
                double       sHi = (b < BINS - 1) ? g_sum[b + 1] : 0.0;
                unsigned int cHi = (b < BINS - 1) ? g_cnt[b + 1] : 0u;
                double       Sb  = g_sum[b] - sHi;
                unsigned int Cb  = g_cnt[b] - cHi;
                if (Cb > 0u) { n++; loss += Sb / (double)Cb; }
            }
            out[0] = (n > 0) ? (float)(loss / (double)n) : 0.0f;
#pragma unroll
            for (int b = 0; b < BINS; b++) { g_sum[b] = 0.0; g_cnt[b] = 0u; }
            g_ticket = 0u;
        }
    }
}

extern "C" void kernel_launch(void* const* d_in, const int* in_sizes, int n_in,
                              void* d_out, int out_size) {
    const float4* pred = (const float4*)d_in[0];
    const float4* targ = (const float4*)d_in[1];
    const float4* lw   = (const float4*)d_in[2];
    float* out = (float*)d_out;

    int n_total = in_sizes[0];
    int n4 = n_total / 4;

    ghmc_kernel<<<GRID_BLOCKS, BLOCK_THREADS>>>(pred, targ, lw, out, n4, n_total);
}

// round 16
// speedup vs baseline: 1.2179x; 1.2179x over previous
#include <cuda_runtime.h>
#include <cuda_fp16.h>

#define BINS 10
#define GRID_BLOCKS 592          // 4 CTAs x 148 SMs, persistent single wave
#define BLOCK_THREADS 256
#define DEPTH 3                  // cp.async ring depth (2 stages in flight)

// Device-global scratch (no allocations allowed). Zero at module load;
// the in-kernel finalizer resets after every launch (graph-replay safe).
__device__ double       g_sum[BINS];   // cumulative: sum over bins >= k
__device__ unsigned int g_cnt[BINS];   // cumulative counts
__device__ unsigned int g_ticket;

// Thresholds (half2 bit patterns) in constant memory:
// [-100 sentinel(validity), log2(1/9), -2, log2(3/7), log2(4/6), 0,
//  log2(6/4), log2(7/3), 2, log2(9)]   (bin>=k <=> q2 >= log2(k/(10-k)))
__constant__ unsigned int c_th2[BINS] = {
    0xD640D640u, 0xC257C257u, 0xC000C000u, 0xBCE4BCE4u, 0xB8AEB8AEu,
    0x00000000u, 0x38AE38AEu, 0x3CE43CE4u, 0x40004000u, 0x42574257u
};

__device__ __forceinline__ void cp16(float4* smem_dst, const float4* gsrc) {
    unsigned int s = (unsigned int)__cvta_generic_to_shared(smem_dst);
    asm volatile("cp.async.cg.shared.global [%0], [%1], 16;"
                 :: "r"(s), "l"(gsrc) : "memory");
}
#define CP_COMMIT()  asm volatile("cp.async.commit_group;" ::: "memory")
#define CP_WAIT(n)   asm volatile("cp.async.wait_group %0;" :: "n"(n) : "memory")

// f32 front end per element. Log2 domain: q2 = p*(1-2t)*log2e.
//   |sigmoid(p)-t| = sigmoid(q),  bce = (q2 + log2(1+2^q2)) * ln2
// Invalid (w==0) elements get q2 = -1000 so every bin mask is false.
__device__ __forceinline__ void ghmc_elem(float p, float t, float w,
                                          float& q2m, float& bw) {
    const float L2E = 1.44269504089f;
    float sgnl = fmaf(-2.0f * L2E, t, L2E);   // (1-2t)*log2e
    float q2   = p * sgnl;
    q2m = (w > 0.0f) ? q2 : -1000.0f;
    float e2 = exp2f(q2);                     // MUFU.EX2
    float l  = __log2f(1.0f + e2);            // FADD + MUFU.LG2
    bw = (q2 + l) * 0.69314718056f;           // softplus in natural units
}

// Pairwise half2 cumulative scatter: per threshold one compare-mask,
// one HFMA2 (sum += mask*bce), one HADD2 (count += mask).
__device__ __forceinline__ void ghmc_acc(__half2 qh, __half2 bh,
                                         __half2* hs, __half2* hc) {
#pragma unroll
    for (int k = 0; k < BINS; k++) {
        __half2 thk = *reinterpret_cast<const __half2*>(&c_th2[k]);
        __half2 m = __hge2(qh, thk);          // 1.0 / 0.0 per half
        hs[k] = __hfma2(m, bh, hs[k]);
        hc[k] = __hadd2(hc[k], m);
    }
}

__device__ __forceinline__ void ghmc_quad(const float4& p, const float4& t,
                                          const float4& w,
                                          __half2* hs, __half2* hc) {
    float qa, qb, ba, bb;
    ghmc_elem(p.x, t.x, w.x, qa, ba);
    ghmc_elem(p.y, t.y, w.y, qb, bb);
    ghmc_acc(__floats2half2_rn(qa, qb), __floats2half2_rn(ba, bb), hs, hc);
    ghmc_elem(p.z, t.z, w.z, qa, ba);
    ghmc_elem(p.w, t.w, w.w, qb, bb);
    ghmc_acc(__floats2half2_rn(qa, qb), __floats2half2_rn(ba, bb), hs, hc);
}

__global__ void __launch_bounds__(BLOCK_THREADS, 4)
ghmc_kernel(const float4* __restrict__ pred,
            const float4* __restrict__ targ,
            const float4* __restrict__ lw,
            float* __restrict__ out,
            int n4, int n_total) {
    // Thread-private staging: thread tid owns s_x[slot*256 + tid].
    // 3 arrays x DEPTH x 256 x 16B = 36 KB static smem.
    __shared__ float4 s_p[DEPTH * BLOCK_THREADS];
    __shared__ float4 s_t[DEPTH * BLOCK_THREADS];
    __shared__ float4 s_w[DEPTH * BLOCK_THREADS];

    __half2 hs[BINS], hc[BINS];
    const __half2 hzero = __halves2half2(__ushort_as_half(0), __ushort_as_half(0));
#pragma unroll
    for (int b = 0; b < BINS; b++) { hs[b] = hzero; hc[b] = hzero; }

    const int tid    = threadIdx.x;
    const int gid    = blockIdx.x * BLOCK_THREADS + tid;
    const int stride = gridDim.x * BLOCK_THREADS;

    // Prologue: prefetch DEPTH-1 = 2 stages. Empty groups (guarded-off cp)
    // complete immediately, keeping group accounting uniform.
#pragma unroll
    for (int k = 0; k < DEPTH - 1; k++) {
        int i = gid + k * stride;
        if (i < n4) {
            cp16(&s_p[k * BLOCK_THREADS + tid], pred + i);
            cp16(&s_t[k * BLOCK_THREADS + tid], targ + i);
            cp16(&s_w[k * BLOCK_THREADS + tid], lw + i);
        }
        CP_COMMIT();
    }

    // Main loop: wait for the oldest stage, consume it (thread-private ->
    // no __syncthreads needed), then refill that slot DEPTH-1 ahead.
    int slot = 0;
    for (int i = gid; i < n4; i += stride) {
        CP_WAIT(DEPTH - 2);                   // oldest group complete
        float4 p = s_p[slot * BLOCK_THREADS + tid];
        float4 t = s_t[slot * BLOCK_THREADS + tid];
        float4 w = s_w[slot * BLOCK_THREADS + tid];

        int ip = i + (DEPTH - 1) * stride;    // prefetch into freed slot
        if (ip < n4) {
            int ps = slot;                    // (slot + DEPTH-1) % DEPTH == slot shifted ring; reuse freed slot
            cp16(&s_p[ps * BLOCK_THREADS + tid], pred + ip);
            cp16(&s_t[ps * BLOCK_THREADS + tid], targ + ip);
            cp16(&s_w[ps * BLOCK_THREADS + tid], lw + ip);
        }
        CP_COMMIT();

        ghmc_quad(p, t, w, hs, hc);

        slot = (slot == DEPTH - 1) ? 0 : slot + 1;
    }
    CP_WAIT(0);                               // drain before smem reuse below

    // Scalar tail (n_total % 4): one thread, second slot invalidated.
    if (gid == 0) {
        const float* pf = (const float*)pred;
        const float* tf = (const float*)targ;
        const float* wf = (const float*)lw;
        for (int k = n4 * 4; k < n_total; k++) {
            float qa, ba;
            ghmc_elem(pf[k], tf[k], wf[k], qa, ba);
            ghmc_acc(__floats2half2_rn(qa, -1000.0f),
                     __floats2half2_rn(ba, 0.0f), hs, hc);
        }
    }

    // Unpack half2 accumulators to f32 (per-thread per-bin counts <= ~143:
    // integers < 2048 are exact in half).
    float s[BINS], c[BINS];
#pragma unroll
    for (int b = 0; b < BINS; b++) {
        float2 sf = __half22float2(hs[b]);
        float2 cf = __half22float2(hc[b]);
        s[b] = sf.x + sf.y;
        c[b] = cf.x + cf.y;
    }

    // Warp butterfly reduce (block counts <= 37k: exact in f32).
#pragma unroll
    for (int b = 0; b < BINS; b++)
#pragma unroll
        for (int off = 16; off > 0; off >>= 1) {
            s[b] += __shfl_xor_sync(0xffffffffu, s[b], off);
            c[b] += __shfl_xor_sync(0xffffffffu, c[b], off);
        }

    __shared__ float s_sum[BINS];
    __shared__ float s_cnt[BINS];
    if (tid < BINS) { s_sum[tid] = 0.0f; s_cnt[tid] = 0.0f; }
    __syncthreads();

    if ((tid & 31) == 0) {
#pragma unroll
        for (int b = 0; b < BINS; b++) {
            atomicAdd(&s_sum[b], s[b]);
            atomicAdd(&s_cnt[b], c[b]);
        }
    }
    __syncthreads();

    if (tid < BINS) {
        atomicAdd(&g_sum[tid], (double)s_sum[tid]);
        atomicAdd(&g_cnt[tid], (unsigned int)(s_cnt[tid] + 0.5f));
    }
    __threadfence();
    __syncthreads();

    // Last block: cumulative -> per-bin, compute loss, reset globals.
    if (tid == 0) {
        unsigned int done = atomicAdd(&g_ticket, 1u);
        if (done == gridDim.x - 1) {
            __threadfence();
            double loss = 0.0;
            int n = 0;
#pragma unroll
            for (int b = 0; b < BINS; b++) {
                double       sHi = (b < BINS - 1) ? g_sum[b + 1] : 0.0;
                unsigned int cHi = (b < BINS - 1) ? g_cnt[b + 1] : 0u;
                double       Sb  = g_sum[b] - sHi;
                unsigned int Cb  = g_cnt[b] - cHi;
                if (Cb > 0u) { n++; loss += Sb / (double)Cb; }
            }
            out[0] = (n > 0) ? (float)(loss / (double)n) : 0.0f;
#pragma unroll
            for (int b = 0; b < BINS; b++) { g_sum[b] = 0.0; g_cnt[b] = 0u; }
            g_ticket = 0u;
        }
    }
}

extern "C" void kernel_launch(void* const* d_in, const int* in_sizes, int n_in,
                              void* d_out, int out_size) {
    const float4* pred = (const float4*)d_in[0];
    const float4* targ = (const float4*)d_in[1];
    const float4* lw   = (const float4*)d_in[2];
    float* out = (float*)d_out;

    int n_total = in_sizes[0];
    int n4 = n_total / 4;

    ghmc_kernel<<<GRID_BLOCKS, BLOCK_THREADS>>>(pred, targ, lw, out, n4, n_total);
}